// round 2
// baseline (speedup 1.0000x reference)
#include <cuda_runtime.h>
#include <cuda_bf16.h>
#include <math.h>

// ---------------------------------------------------------------------------
// stack_latent_attention: B=16, NV=NH=1024, D=1024
//
// Pipeline:
//   Vp  = v @ Wv.T + Wv_b            [16384,1024]
//   Q   = v @ qv.T + qv_b            [16384,1024]
//   Hh  = h @ Wh.T                   [16384,1024]
//   Key = h @ kh.T  (mask rows)      [16384,1024]
//   Zp  = z @ Wz.T                   [16384,1024]  (K=2048)
//   att = Q_b @ Key_b.T              [16,1024,1024]
//   att = softmax_rows(att)
//   Hv  = att_b @ Hh_b               [16,1024,1024]
//   s   = sigmoid(Vp+Hv+Zp) -> z_new[...,  :1024]
//   u   = s . Wu                     [16384]
//   p_b = softmax(u_b masked)        [16,1024]
//   g   = sum_j p[b,j] * v[b,j,:]    [16,1024]
//   h_new[b,i,:] = g[b,:]   (f rows are identical: u_i cancels in softmax_j)
//   z_new[b,i,1024:2048] = g[b,:]
// ---------------------------------------------------------------------------

#define BB    16
#define NVV   1024
#define DD    1024
#define MROWS (BB * NVV)          // 16384
#define NEGV  (-1e30f)

// ------------------- scratch (device globals; no allocation) ---------------
__device__ float g_Vp [MROWS * DD];
__device__ float g_Q  [MROWS * DD];
__device__ float g_Hh [MROWS * DD];
__device__ float g_Key[MROWS * DD];
__device__ float g_Zp [MROWS * DD];
__device__ float g_att[BB * NVV * NVV];
__device__ float g_Hv [MROWS * DD];
__device__ float g_u  [MROWS];
__device__ float g_p  [MROWS];
__device__ float g_g  [BB * DD];

// ------------------------------- GEMM --------------------------------------
// C[m,n] = sum_k A[m,k] * B'[k,n]  (+bias[n])  (mask row -> NEG)
// BT=true : B stored [N,K] row-major (NT gemm, i.e. A @ B.T)
// BT=false: B stored [K,N] row-major (NN gemm)
// Batched along blockIdx.z with element strides sA,sB,sC.
#define TM 128
#define TN 128
#define TK 16

template <bool BT>
__global__ __launch_bounds__(256)
void gemm_kernel(const float* __restrict__ A, const float* __restrict__ B,
                 const float* __restrict__ bias, const int* __restrict__ mask,
                 float* __restrict__ C,
                 int M, int N, int K,
                 long long sA, long long sB, long long sC)
{
    __shared__ float As[TK][TM];
    __shared__ float Bs[TK][TN];

    const int bz = blockIdx.z;
    A += (long long)bz * sA;
    B += (long long)bz * sB;
    C += (long long)bz * sC;

    const int m0 = blockIdx.y * TM;
    const int n0 = blockIdx.x * TN;
    const int tid = threadIdx.x;

    const int tm = (tid / 16) * 8;
    const int tn = (tid % 16) * 8;

    float acc[8][8];
#pragma unroll
    for (int i = 0; i < 8; i++)
#pragma unroll
        for (int j = 0; j < 8; j++) acc[i][j] = 0.f;

    for (int k0 = 0; k0 < K; k0 += TK) {
        // A tile: 128 rows x 16 k, A row-major [M,K]
#pragma unroll
        for (int it = 0; it < 2; it++) {
            int i   = tid + it * 256;            // 0..511
            int row = i >> 2;                    // /4
            int kq  = (i & 3) * 4;
            float4 va = *(const float4*)(A + (long long)(m0 + row) * K + k0 + kq);
            As[kq + 0][row] = va.x;
            As[kq + 1][row] = va.y;
            As[kq + 2][row] = va.z;
            As[kq + 3][row] = va.w;
        }
        if (BT) {
            // B tile from [N,K]: same pattern as A
#pragma unroll
            for (int it = 0; it < 2; it++) {
                int i   = tid + it * 256;
                int row = i >> 2;
                int kq  = (i & 3) * 4;
                float4 vb = *(const float4*)(B + (long long)(n0 + row) * K + k0 + kq);
                Bs[kq + 0][row] = vb.x;
                Bs[kq + 1][row] = vb.y;
                Bs[kq + 2][row] = vb.z;
                Bs[kq + 3][row] = vb.w;
            }
        } else {
            // B tile from [K,N]: direct copy, coalesced along n
#pragma unroll
            for (int it = 0; it < 2; it++) {
                int i  = tid + it * 256;
                int kk = i >> 5;                 // /32
                int nq = (i & 31) * 4;
                float4 vb = *(const float4*)(B + (long long)(k0 + kk) * N + n0 + nq);
                *(float4*)&Bs[kk][nq] = vb;
            }
        }
        __syncthreads();

#pragma unroll
        for (int kk = 0; kk < TK; kk++) {
            float a[8], b[8];
            *(float4*)&a[0] = *(const float4*)&As[kk][tm];
            *(float4*)&a[4] = *(const float4*)&As[kk][tm + 4];
            *(float4*)&b[0] = *(const float4*)&Bs[kk][tn];
            *(float4*)&b[4] = *(const float4*)&Bs[kk][tn + 4];
#pragma unroll
            for (int i = 0; i < 8; i++)
#pragma unroll
                for (int j = 0; j < 8; j++)
                    acc[i][j] = fmaf(a[i], b[j], acc[i][j]);
        }
        __syncthreads();
    }

    // epilogue
#pragma unroll
    for (int i = 0; i < 8; i++) {
        int m = m0 + tm + i;
        bool masked = (mask != nullptr) && (mask[m] == 0);
        float vals[8];
#pragma unroll
        for (int j = 0; j < 8; j++) {
            float x = acc[i][j];
            if (bias) x += bias[n0 + tn + j];
            if (masked) x = NEGV;
            vals[j] = x;
        }
        float* cp = C + (long long)m * N + n0 + tn;
        *(float4*)&cp[0] = *(float4*)&vals[0];
        *(float4*)&cp[4] = *(float4*)&vals[4];
    }
}

// -------------------------- row softmax (cols=1024) -------------------------
__global__ __launch_bounds__(256)
void softmax_rows_kernel(float* __restrict__ att)
{
    __shared__ float red[256];
    const int row = blockIdx.x;
    float* p = att + (long long)row * NVV;
    const int tid = threadIdx.x;

    float mx = -INFINITY;
    for (int c = tid; c < NVV; c += 256) mx = fmaxf(mx, p[c]);
    red[tid] = mx; __syncthreads();
    for (int s = 128; s > 0; s >>= 1) {
        if (tid < s) red[tid] = fmaxf(red[tid], red[tid + s]);
        __syncthreads();
    }
    mx = red[0]; __syncthreads();

    float sum = 0.f;
    for (int c = tid; c < NVV; c += 256) {
        float e = __expf(p[c] - mx);
        p[c] = e;
        sum += e;
    }
    red[tid] = sum; __syncthreads();
    for (int s = 128; s > 0; s >>= 1) {
        if (tid < s) red[tid] += red[tid + s];
        __syncthreads();
    }
    float inv = 1.f / red[0];
    for (int c = tid; c < NVV; c += 256) p[c] *= inv;
}

// ------------------ s = sigmoid(Vp+Hv+Zp) -> z_new[:, :D] -------------------
__global__ __launch_bounds__(256)
void s_kernel(const float* __restrict__ Vp, const float* __restrict__ Hv,
              const float* __restrict__ Zp, float* __restrict__ zout)
{
    long long i = (long long)blockIdx.x * 256 + threadIdx.x; // < 16777216
    float x = Vp[i] + Hv[i] + Zp[i];
    float s = 1.f / (1.f + __expf(-x));
    long long row = i >> 10;
    int col = (int)(i & 1023);
    zout[row * 2048 + col] = s;
}

// --------------------------- u[row] = s_row . Wu ----------------------------
__global__ __launch_bounds__(256)
void u_kernel(const float* __restrict__ zout, const float* __restrict__ Wu,
              float* __restrict__ u)
{
    __shared__ float red[256];
    const int row = blockIdx.x;
    const float* s = zout + (long long)row * 2048;  // s lives in z_new[:, :1024]
    const int tid = threadIdx.x;
    float acc = 0.f;
    for (int d = tid; d < DD; d += 256) acc = fmaf(s[d], Wu[d], acc);
    red[tid] = acc; __syncthreads();
    for (int st = 128; st > 0; st >>= 1) {
        if (tid < st) red[tid] += red[tid + st];
        __syncthreads();
    }
    if (tid == 0) u[row] = red[0];
}

// ----------------- per-batch softmax of u (with v_mask) ---------------------
__global__ __launch_bounds__(256)
void p_kernel(const float* __restrict__ u, const int* __restrict__ v_mask,
              float* __restrict__ p)
{
    __shared__ float red[256];
    __shared__ float vals[NVV];
    const int b = blockIdx.x;
    const int tid = threadIdx.x;

    float mx = -INFINITY;
    for (int j = tid; j < NVV; j += 256) {
        float val = (v_mask[b * NVV + j] == 0) ? NEGV : u[b * NVV + j];
        vals[j] = val;
        mx = fmaxf(mx, val);
    }
    red[tid] = mx; __syncthreads();
    for (int s = 128; s > 0; s >>= 1) {
        if (tid < s) red[tid] = fmaxf(red[tid], red[tid + s]);
        __syncthreads();
    }
    mx = red[0]; __syncthreads();

    float sum = 0.f;
    for (int j = tid; j < NVV; j += 256) {
        float e = __expf(vals[j] - mx);
        vals[j] = e;
        sum += e;
    }
    red[tid] = sum; __syncthreads();
    for (int s = 128; s > 0; s >>= 1) {
        if (tid < s) red[tid] += red[tid + s];
        __syncthreads();
    }
    float inv = 1.f / red[0];
    for (int j = tid; j < NVV; j += 256) p[b * NVV + j] = vals[j] * inv;
}

// ----------------------- g[b,d] = sum_j p[b,j] v[b,j,d] ---------------------
__global__ __launch_bounds__(256)
void g_kernel(const float* __restrict__ p, const float* __restrict__ v,
              float* __restrict__ g)
{
    __shared__ float ps[NVV];
    const int b = blockIdx.y;
    const int tid = threadIdx.x;
    for (int j = tid; j < NVV; j += 256) ps[j] = p[b * NVV + j];
    __syncthreads();

    const int d = blockIdx.x * 256 + tid;
    const float* vb = v + (long long)b * NVV * DD;
    float acc = 0.f;
#pragma unroll 4
    for (int j = 0; j < NVV; j++)
        acc = fmaf(ps[j], vb[(long long)j * DD + d], acc);
    g[b * DD + d] = acc;
}

// ------------- broadcast: h_new[b,i,:]=g[b,:], z_new[b,i,D: ]=g[b,:] --------
__global__ __launch_bounds__(256)
void bcast_kernel(const float* __restrict__ g, float* __restrict__ hnew,
                  float* __restrict__ zout)
{
    long long i = (long long)blockIdx.x * 256 + threadIdx.x; // < 16777216
    int d = (int)(i & 1023);
    long long bi = i >> 10;          // global row b*1024+i
    int b = (int)(bi >> 10);
    float val = g[b * DD + d];
    hnew[i] = val;
    zout[bi * 2048 + DD + d] = val;
}

// ------------------------------- launch ------------------------------------
extern "C" void kernel_launch(void* const* d_in, const int* in_sizes, int n_in,
                              void* d_out, int out_size)
{
    const float* v      = (const float*)d_in[0];
    const float* h      = (const float*)d_in[1];
    const float* z      = (const float*)d_in[2];
    const int*   v_mask = (const int*)  d_in[3];
    const int*   h_mask = (const int*)  d_in[4];
    const float* Wv_w   = (const float*)d_in[5];
    const float* Wv_b   = (const float*)d_in[6];
    const float* Wh_w   = (const float*)d_in[7];
    const float* qv_w   = (const float*)d_in[8];
    const float* qv_b   = (const float*)d_in[9];
    const float* kh_w   = (const float*)d_in[10];
    const float* Wz_w   = (const float*)d_in[11];
    const float* Wu_w   = (const float*)d_in[12];

    float* out  = (float*)d_out;
    float* hnew = out;                                  // [16,1024,1024]
    float* zout = out + (long long)MROWS * DD;          // [16,1024,2048]

    float *Vp, *Q, *Hh, *Key, *Zp, *Att, *Hv, *U, *P, *G;
    cudaGetSymbolAddress((void**)&Vp,  g_Vp);
    cudaGetSymbolAddress((void**)&Q,   g_Q);
    cudaGetSymbolAddress((void**)&Hh,  g_Hh);
    cudaGetSymbolAddress((void**)&Key, g_Key);
    cudaGetSymbolAddress((void**)&Zp,  g_Zp);
    cudaGetSymbolAddress((void**)&Att, g_att);
    cudaGetSymbolAddress((void**)&Hv,  g_Hv);
    cudaGetSymbolAddress((void**)&U,   g_u);
    cudaGetSymbolAddress((void**)&P,   g_p);
    cudaGetSymbolAddress((void**)&G,   g_g);

    const long long PB = (long long)NVV * NVV; // 1048576 per-batch stride

    dim3 gBig(DD / TN, MROWS / TM, 1);   // (8,128,1)
    dim3 gBat(DD / TN, NVV / TM, BB);    // (8,8,16)

    // 5 input projections (single big GEMM each; weights shared across batch)
    gemm_kernel<true><<<gBig, 256>>>(v, Wv_w, Wv_b, nullptr, Vp,  MROWS, DD, DD,   0, 0, 0);
    gemm_kernel<true><<<gBig, 256>>>(v, qv_w, qv_b, nullptr, Q,   MROWS, DD, DD,   0, 0, 0);
    gemm_kernel<true><<<gBig, 256>>>(h, Wh_w, nullptr, nullptr, Hh, MROWS, DD, DD, 0, 0, 0);
    gemm_kernel<true><<<gBig, 256>>>(h, kh_w, nullptr, h_mask, Key, MROWS, DD, DD, 0, 0, 0);
    gemm_kernel<true><<<gBig, 256>>>(z, Wz_w, nullptr, nullptr, Zp, MROWS, DD, 2 * DD, 0, 0, 0);

    // attention
    gemm_kernel<true><<<gBat, 256>>>(Q, Key, nullptr, nullptr, Att, NVV, NVV, DD, PB, PB, PB);
    softmax_rows_kernel<<<MROWS, 256>>>(Att);
    gemm_kernel<false><<<gBat, 256>>>(Att, Hh, nullptr, nullptr, Hv, NVV, DD, NVV, PB, PB, PB);

    // s -> z_new[:, :D], then u, p, g, broadcast
    s_kernel<<<(MROWS * DD) / 256, 256>>>(Vp, Hv, Zp, zout);
    u_kernel<<<MROWS, 256>>>(zout, Wu_w, U);
    p_kernel<<<BB, 256>>>(U, v_mask, P);
    g_kernel<<<dim3(DD / 256, BB), 256>>>(P, v, G);
    bcast_kernel<<<(MROWS * DD) / 256, 256>>>(G, hnew, zout);
}

// round 3
// speedup vs baseline: 1.0002x; 1.0002x over previous
#include <cuda_runtime.h>
#include <cuda_bf16.h>
#include <math.h>

// ---------------------------------------------------------------------------
// stack_latent_attention: B=16, NV=NH=1024, D=1024
//
// Pipeline:
//   Vp  = v @ Wv.T + Wv_b            [16384,1024]
//   Q   = v @ qv.T + qv_b            [16384,1024]
//   Hh  = h @ Wh.T                   [16384,1024]
//   Key = h @ kh.T  (mask rows)      [16384,1024]
//   Zp  = z @ Wz.T                   [16384,1024]  (K=2048)
//   att = Q_b @ Key_b.T              [16,1024,1024]
//   att = softmax_rows(att)
//   Hv  = att_b @ Hh_b               [16,1024,1024]
//   s   = sigmoid(Vp+Hv+Zp) -> z_new[...,  :1024]
//   u   = s . Wu                     [16384]
//   p_b = softmax(u_b masked)        [16,1024]
//   g   = sum_j p[b,j] * v[b,j,:]    [16,1024]
//   h_new[b,i,:] = g[b,:]   (f rows are identical: u_i cancels in softmax_j)
//   z_new[b,i,1024:2048] = g[b,:]
// ---------------------------------------------------------------------------

#define BB    16
#define NVV   1024
#define DD    1024
#define MROWS (BB * NVV)          // 16384
#define NEGV  (-1e30f)

// ------------------- scratch (device globals; no allocation) ---------------
__device__ float g_Vp [MROWS * DD];
__device__ float g_Q  [MROWS * DD];
__device__ float g_Hh [MROWS * DD];
__device__ float g_Key[MROWS * DD];
__device__ float g_Zp [MROWS * DD];
__device__ float g_att[BB * NVV * NVV];
__device__ float g_Hv [MROWS * DD];
__device__ float g_u  [MROWS];
__device__ float g_p  [MROWS];
__device__ float g_g  [BB * DD];

// ------------------------------- GEMM --------------------------------------
// C[m,n] = sum_k A[m,k] * B'[k,n]  (+bias[n])  (mask row -> NEG)
// BT=true : B stored [N,K] row-major (NT gemm, i.e. A @ B.T)
// BT=false: B stored [K,N] row-major (NN gemm)
// Batched along blockIdx.z with element strides sA,sB,sC.
#define TM 128
#define TN 128
#define TK 16

template <bool BT>
__global__ __launch_bounds__(256)
void gemm_kernel(const float* __restrict__ A, const float* __restrict__ B,
                 const float* __restrict__ bias, const int* __restrict__ mask,
                 float* __restrict__ C,
                 int M, int N, int K,
                 long long sA, long long sB, long long sC)
{
    __shared__ float As[TK][TM];
    __shared__ float Bs[TK][TN];

    const int bz = blockIdx.z;
    A += (long long)bz * sA;
    B += (long long)bz * sB;
    C += (long long)bz * sC;

    const int m0 = blockIdx.y * TM;
    const int n0 = blockIdx.x * TN;
    const int tid = threadIdx.x;

    const int tm = (tid / 16) * 8;
    const int tn = (tid % 16) * 8;

    float acc[8][8];
#pragma unroll
    for (int i = 0; i < 8; i++)
#pragma unroll
        for (int j = 0; j < 8; j++) acc[i][j] = 0.f;

    for (int k0 = 0; k0 < K; k0 += TK) {
        // A tile: 128 rows x 16 k, A row-major [M,K]
#pragma unroll
        for (int it = 0; it < 2; it++) {
            int i   = tid + it * 256;            // 0..511
            int row = i >> 2;                    // /4
            int kq  = (i & 3) * 4;
            float4 va = *(const float4*)(A + (long long)(m0 + row) * K + k0 + kq);
            As[kq + 0][row] = va.x;
            As[kq + 1][row] = va.y;
            As[kq + 2][row] = va.z;
            As[kq + 3][row] = va.w;
        }
        if (BT) {
            // B tile from [N,K]: same pattern as A
#pragma unroll
            for (int it = 0; it < 2; it++) {
                int i   = tid + it * 256;
                int row = i >> 2;
                int kq  = (i & 3) * 4;
                float4 vb = *(const float4*)(B + (long long)(n0 + row) * K + k0 + kq);
                Bs[kq + 0][row] = vb.x;
                Bs[kq + 1][row] = vb.y;
                Bs[kq + 2][row] = vb.z;
                Bs[kq + 3][row] = vb.w;
            }
        } else {
            // B tile from [K,N]: direct copy, coalesced along n
#pragma unroll
            for (int it = 0; it < 2; it++) {
                int i  = tid + it * 256;
                int kk = i >> 5;                 // /32
                int nq = (i & 31) * 4;
                float4 vb = *(const float4*)(B + (long long)(k0 + kk) * N + n0 + nq);
                *(float4*)&Bs[kk][nq] = vb;
            }
        }
        __syncthreads();

#pragma unroll
        for (int kk = 0; kk < TK; kk++) {
            float a[8], b[8];
            *(float4*)&a[0] = *(const float4*)&As[kk][tm];
            *(float4*)&a[4] = *(const float4*)&As[kk][tm + 4];
            *(float4*)&b[0] = *(const float4*)&Bs[kk][tn];
            *(float4*)&b[4] = *(const float4*)&Bs[kk][tn + 4];
#pragma unroll
            for (int i = 0; i < 8; i++)
#pragma unroll
                for (int j = 0; j < 8; j++)
                    acc[i][j] = fmaf(a[i], b[j], acc[i][j]);
        }
        __syncthreads();
    }

    // epilogue
#pragma unroll
    for (int i = 0; i < 8; i++) {
        int m = m0 + tm + i;
        bool masked = (mask != nullptr) && (mask[m] == 0);
        float vals[8];
#pragma unroll
        for (int j = 0; j < 8; j++) {
            float x = acc[i][j];
            if (bias) x += bias[n0 + tn + j];
            if (masked) x = NEGV;
            vals[j] = x;
        }
        float* cp = C + (long long)m * N + n0 + tn;
        *(float4*)&cp[0] = *(float4*)&vals[0];
        *(float4*)&cp[4] = *(float4*)&vals[4];
    }
}

// -------------------------- row softmax (cols=1024) -------------------------
__global__ __launch_bounds__(256)
void softmax_rows_kernel(float* __restrict__ att)
{
    __shared__ float red[256];
    const int row = blockIdx.x;
    float* p = att + (long long)row * NVV;
    const int tid = threadIdx.x;

    float mx = -INFINITY;
    for (int c = tid; c < NVV; c += 256) mx = fmaxf(mx, p[c]);
    red[tid] = mx; __syncthreads();
    for (int s = 128; s > 0; s >>= 1) {
        if (tid < s) red[tid] = fmaxf(red[tid], red[tid + s]);
        __syncthreads();
    }
    mx = red[0]; __syncthreads();

    float sum = 0.f;
    for (int c = tid; c < NVV; c += 256) {
        float e = __expf(p[c] - mx);
        p[c] = e;
        sum += e;
    }
    red[tid] = sum; __syncthreads();
    for (int s = 128; s > 0; s >>= 1) {
        if (tid < s) red[tid] += red[tid + s];
        __syncthreads();
    }
    float inv = 1.f / red[0];
    for (int c = tid; c < NVV; c += 256) p[c] *= inv;
}

// ------------------ s = sigmoid(Vp+Hv+Zp) -> z_new[:, :D] -------------------
__global__ __launch_bounds__(256)
void s_kernel(const float* __restrict__ Vp, const float* __restrict__ Hv,
              const float* __restrict__ Zp, float* __restrict__ zout)
{
    long long i = (long long)blockIdx.x * 256 + threadIdx.x; // < 16777216
    float x = Vp[i] + Hv[i] + Zp[i];
    float s = 1.f / (1.f + __expf(-x));
    long long row = i >> 10;
    int col = (int)(i & 1023);
    zout[row * 2048 + col] = s;
}

// --------------------------- u[row] = s_row . Wu ----------------------------
__global__ __launch_bounds__(256)
void u_kernel(const float* __restrict__ zout, const float* __restrict__ Wu,
              float* __restrict__ u)
{
    __shared__ float red[256];
    const int row = blockIdx.x;
    const float* s = zout + (long long)row * 2048;  // s lives in z_new[:, :1024]
    const int tid = threadIdx.x;
    float acc = 0.f;
    for (int d = tid; d < DD; d += 256) acc = fmaf(s[d], Wu[d], acc);
    red[tid] = acc; __syncthreads();
    for (int st = 128; st > 0; st >>= 1) {
        if (tid < st) red[tid] += red[tid + st];
        __syncthreads();
    }
    if (tid == 0) u[row] = red[0];
}

// ----------------- per-batch softmax of u (with v_mask) ---------------------
__global__ __launch_bounds__(256)
void p_kernel(const float* __restrict__ u, const int* __restrict__ v_mask,
              float* __restrict__ p)
{
    __shared__ float red[256];
    __shared__ float vals[NVV];
    const int b = blockIdx.x;
    const int tid = threadIdx.x;

    float mx = -INFINITY;
    for (int j = tid; j < NVV; j += 256) {
        float val = (v_mask[b * NVV + j] == 0) ? NEGV : u[b * NVV + j];
        vals[j] = val;
        mx = fmaxf(mx, val);
    }
    red[tid] = mx; __syncthreads();
    for (int s = 128; s > 0; s >>= 1) {
        if (tid < s) red[tid] = fmaxf(red[tid], red[tid + s]);
        __syncthreads();
    }
    mx = red[0]; __syncthreads();

    float sum = 0.f;
    for (int j = tid; j < NVV; j += 256) {
        float e = __expf(vals[j] - mx);
        vals[j] = e;
        sum += e;
    }
    red[tid] = sum; __syncthreads();
    for (int s = 128; s > 0; s >>= 1) {
        if (tid < s) red[tid] += red[tid + s];
        __syncthreads();
    }
    float inv = 1.f / red[0];
    for (int j = tid; j < NVV; j += 256) p[b * NVV + j] = vals[j] * inv;
}

// ----------------------- g[b,d] = sum_j p[b,j] v[b,j,d] ---------------------
__global__ __launch_bounds__(256)
void g_kernel(const float* __restrict__ p, const float* __restrict__ v,
              float* __restrict__ g)
{
    __shared__ float ps[NVV];
    const int b = blockIdx.y;
    const int tid = threadIdx.x;
    for (int j = tid; j < NVV; j += 256) ps[j] = p[b * NVV + j];
    __syncthreads();

    const int d = blockIdx.x * 256 + tid;
    const float* vb = v + (long long)b * NVV * DD;
    float acc = 0.f;
#pragma unroll 4
    for (int j = 0; j < NVV; j++)
        acc = fmaf(ps[j], vb[(long long)j * DD + d], acc);
    g[b * DD + d] = acc;
}

// ------------- broadcast: h_new[b,i,:]=g[b,:], z_new[b,i,D: ]=g[b,:] --------
__global__ __launch_bounds__(256)
void bcast_kernel(const float* __restrict__ g, float* __restrict__ hnew,
                  float* __restrict__ zout)
{
    long long i = (long long)blockIdx.x * 256 + threadIdx.x; // < 16777216
    int d = (int)(i & 1023);
    long long bi = i >> 10;          // global row b*1024+i
    int b = (int)(bi >> 10);
    float val = g[b * DD + d];
    hnew[i] = val;
    zout[bi * 2048 + DD + d] = val;
}

// ------------------------------- launch ------------------------------------
extern "C" void kernel_launch(void* const* d_in, const int* in_sizes, int n_in,
                              void* d_out, int out_size)
{
    const float* v      = (const float*)d_in[0];
    const float* h      = (const float*)d_in[1];
    const float* z      = (const float*)d_in[2];
    const int*   v_mask = (const int*)  d_in[3];
    const int*   h_mask = (const int*)  d_in[4];
    const float* Wv_w   = (const float*)d_in[5];
    const float* Wv_b   = (const float*)d_in[6];
    const float* Wh_w   = (const float*)d_in[7];
    const float* qv_w   = (const float*)d_in[8];
    const float* qv_b   = (const float*)d_in[9];
    const float* kh_w   = (const float*)d_in[10];
    const float* Wz_w   = (const float*)d_in[11];
    const float* Wu_w   = (const float*)d_in[12];

    float* out  = (float*)d_out;
    float* hnew = out;                                  // [16,1024,1024]
    float* zout = out + (long long)MROWS * DD;          // [16,1024,2048]

    float *Vp, *Q, *Hh, *Key, *Zp, *Att, *Hv, *U, *P, *G;
    cudaGetSymbolAddress((void**)&Vp,  g_Vp);
    cudaGetSymbolAddress((void**)&Q,   g_Q);
    cudaGetSymbolAddress((void**)&Hh,  g_Hh);
    cudaGetSymbolAddress((void**)&Key, g_Key);
    cudaGetSymbolAddress((void**)&Zp,  g_Zp);
    cudaGetSymbolAddress((void**)&Att, g_att);
    cudaGetSymbolAddress((void**)&Hv,  g_Hv);
    cudaGetSymbolAddress((void**)&U,   g_u);
    cudaGetSymbolAddress((void**)&P,   g_p);
    cudaGetSymbolAddress((void**)&G,   g_g);

    const long long PB = (long long)NVV * NVV; // 1048576 per-batch stride

    dim3 gBig(DD / TN, MROWS / TM, 1);   // (8,128,1)
    dim3 gBat(DD / TN, NVV / TM, BB);    // (8,8,16)

    // 5 input projections (single big GEMM each; weights shared across batch)
    gemm_kernel<true><<<gBig, 256>>>(v, Wv_w, Wv_b, nullptr, Vp,  MROWS, DD, DD,   0, 0, 0);
    gemm_kernel<true><<<gBig, 256>>>(v, qv_w, qv_b, nullptr, Q,   MROWS, DD, DD,   0, 0, 0);
    gemm_kernel<true><<<gBig, 256>>>(h, Wh_w, nullptr, nullptr, Hh, MROWS, DD, DD, 0, 0, 0);
    gemm_kernel<true><<<gBig, 256>>>(h, kh_w, nullptr, h_mask, Key, MROWS, DD, DD, 0, 0, 0);
    gemm_kernel<true><<<gBig, 256>>>(z, Wz_w, nullptr, nullptr, Zp, MROWS, DD, 2 * DD, 0, 0, 0);

    // attention
    gemm_kernel<true><<<gBat, 256>>>(Q, Key, nullptr, nullptr, Att, NVV, NVV, DD, PB, PB, PB);
    softmax_rows_kernel<<<MROWS, 256>>>(Att);
    gemm_kernel<false><<<gBat, 256>>>(Att, Hh, nullptr, nullptr, Hv, NVV, DD, NVV, PB, PB, PB);

    // s -> z_new[:, :D], then u, p, g, broadcast
    s_kernel<<<(MROWS * DD) / 256, 256>>>(Vp, Hv, Zp, zout);
    u_kernel<<<MROWS, 256>>>(zout, Wu_w, U);
    p_kernel<<<BB, 256>>>(U, v_mask, P);
    g_kernel<<<dim3(DD / 256, BB), 256>>>(P, v, G);
    bcast_kernel<<<(MROWS * DD) / 256, 256>>>(G, hnew, zout);
}

// round 5
// speedup vs baseline: 2.3850x; 2.3845x over previous
#include <cuda_runtime.h>
#include <cuda_bf16.h>
#include <cstdint>
#include <math.h>

// ---------------------------------------------------------------------------
// stack_latent_attention (B=16, NV=NH=D=1024)
// GEMMs via mma.sync.m16n8k16 bf16 (baseline PTX, valid on compute_103),
// split-bf16 3-term for fp32-grade accuracy: C += Ah*Bh + Ah*Bl + Al*Bh.
// ---------------------------------------------------------------------------

#define BB    16
#define NVV   1024
#define DD    1024
#define MROWS (BB * NVV)
#define NEGV  (-1e30f)

// ============================ PTX helpers ===================================
__device__ __forceinline__ uint32_t smem_u32(const void* p) {
    uint32_t a;
    asm("{ .reg .u64 t; cvta.to.shared.u64 t, %1; cvt.u32.u64 %0, t; }"
        : "=r"(a) : "l"(p));
    return a;
}

#define CP16(s, g) \
    asm volatile("cp.async.cg.shared.global [%0], [%1], 16;" \
                 :: "r"(s), "l"(g) : "memory")

#define LDSM4(r, addr) \
    asm volatile("ldmatrix.sync.aligned.m8n8.x4.shared.b16 {%0,%1,%2,%3}, [%4];" \
                 : "=r"((r)[0]), "=r"((r)[1]), "=r"((r)[2]), "=r"((r)[3]) \
                 : "r"(addr))

#define MMA(c, a, b0, b1) \
    asm volatile("mma.sync.aligned.m16n8k16.row.col.f32.bf16.bf16.f32 " \
                 "{%0,%1,%2,%3}, {%4,%5,%6,%7}, {%8,%9}, {%0,%1,%2,%3};" \
                 : "+f"((c)[0]), "+f"((c)[1]), "+f"((c)[2]), "+f"((c)[3]) \
                 : "r"((a)[0]), "r"((a)[1]), "r"((a)[2]), "r"((a)[3]), \
                   "r"(b0), "r"(b1))

// ============================ scratch =======================================
__device__ __align__(256) __nv_bfloat16 g_vhi[MROWS * DD], g_vlo[MROWS * DD];
__device__ __align__(256) __nv_bfloat16 g_hhi[MROWS * DD], g_hlo[MROWS * DD];
__device__ __align__(256) __nv_bfloat16 g_zhi[MROWS * 2 * DD], g_zlo[MROWS * 2 * DD];
__device__ __align__(256) __nv_bfloat16 g_Wvh[DD * DD], g_Wvl[DD * DD];
__device__ __align__(256) __nv_bfloat16 g_qvh[DD * DD], g_qvl[DD * DD];
__device__ __align__(256) __nv_bfloat16 g_Whh[DD * DD], g_Whl[DD * DD];
__device__ __align__(256) __nv_bfloat16 g_khh[DD * DD], g_khl[DD * DD];
__device__ __align__(256) __nv_bfloat16 g_Wzh[DD * 2 * DD], g_Wzl[DD * 2 * DD];
__device__ __align__(256) __nv_bfloat16 g_Qh[MROWS * DD],  g_Ql[MROWS * DD];
__device__ __align__(256) __nv_bfloat16 g_Kh[MROWS * DD],  g_Kl[MROWS * DD];
__device__ __align__(256) __nv_bfloat16 g_Ph[MROWS * DD],  g_Pl[MROWS * DD];
__device__ __align__(256) __nv_bfloat16 g_HTh[MROWS * DD], g_HTl[MROWS * DD];
__device__ __align__(256) float g_Vp[MROWS * DD];
__device__ __align__(256) float g_Hh[MROWS * DD];
__device__ __align__(256) float g_Zp[MROWS * DD];
__device__ __align__(256) float g_att[(long long)BB * NVV * NVV];
__device__ __align__(256) float g_Hv[MROWS * DD];
__device__ float g_u[MROWS];
__device__ float g_p[MROWS];
__device__ float g_g[BB * DD];

// ======================== conversion kernels ================================
__global__ __launch_bounds__(256)
void conv_split(const float* __restrict__ x, __nv_bfloat16* __restrict__ hi,
                __nv_bfloat16* __restrict__ lo, long long n4)
{
    long long i = (long long)blockIdx.x * 256 + threadIdx.x;
    if (i >= n4) return;
    float4 v = ((const float4*)x)[i];
    __nv_bfloat16 hh[4], ll[4];
    float f[4] = {v.x, v.y, v.z, v.w};
#pragma unroll
    for (int k = 0; k < 4; k++) {
        hh[k] = __float2bfloat16(f[k]);
        ll[k] = __float2bfloat16(f[k] - __bfloat162float(hh[k]));
    }
    *(uint2*)(hi + 4 * i) = *(uint2*)hh;
    *(uint2*)(lo + 4 * i) = *(uint2*)ll;
}

// Hh fp32 [b, k(1024), n(1024)]  ->  HhT split bf16 [b, n, k]
__global__ void transconv_kernel(const float* __restrict__ X,
                                 __nv_bfloat16* __restrict__ Th,
                                 __nv_bfloat16* __restrict__ Tl)
{
    __shared__ float t[32][33];
    const int b = blockIdx.z;
    const int k0 = blockIdx.x * 32, n0 = blockIdx.y * 32;
    const int tx = threadIdx.x, ty = threadIdx.y;   // 32 x 8
    const float* src = X + (long long)b * NVV * DD;
    for (int i = ty; i < 32; i += 8)
        t[i][tx] = src[(long long)(k0 + i) * DD + n0 + tx];
    __syncthreads();
    __nv_bfloat16* dh = Th + (long long)b * NVV * DD;
    __nv_bfloat16* dl = Tl + (long long)b * NVV * DD;
    for (int i = ty; i < 32; i += 8) {
        float v = t[tx][i];
        __nv_bfloat16 h = __float2bfloat16(v);
        long long o = (long long)(n0 + i) * DD + k0 + tx;
        dh[o] = h;
        dl[o] = __float2bfloat16(v - __bfloat162float(h));
    }
}

// ============================ mma.sync GEMM =================================
// C[M,N] = sum_k (Ah+Al)[m,k] * (Bh+Bl)[n,k]  (dropping Al*Bl)
// CTA tile 128x128, BK=64, 2-stage cp.async pipeline.
// 8 warps as 2(M) x 4(N); warp tile 64x32 (4 m16-tiles x 4 n8-tiles).
#define BM   128
#define BN   128
#define BKC  64
#define PADK 72                       // row stride in bf16 elems (144 B)
#define ARR  (BM * PADK * 2)          // 18432 B per operand array
#define STAGE (4 * ARR)               // Ah | Al | Bh | Bl = 73728 B
#define SMEM_GEMM (2 * STAGE)         // 147456 B

__global__ __launch_bounds__(256)
void gemm_split(const __nv_bfloat16* __restrict__ Ahi, const __nv_bfloat16* __restrict__ Alo,
                const __nv_bfloat16* __restrict__ Bhi, const __nv_bfloat16* __restrict__ Blo,
                const float* __restrict__ bias, const int* __restrict__ mask,
                float* __restrict__ Cf,
                __nv_bfloat16* __restrict__ Chi, __nv_bfloat16* __restrict__ Clo,
                int K, int ldc,
                long long sA, long long sB, long long sC)
{
    extern __shared__ char smem[];
    const uint32_t sb = smem_u32(smem);
    const int tid = threadIdx.x;
    const int bz = blockIdx.z;
    Ahi += (long long)bz * sA;  Alo += (long long)bz * sA;
    Bhi += (long long)bz * sB;  Blo += (long long)bz * sB;
    const long long coff = (long long)bz * sC;
    const int m0 = blockIdx.y * BM;
    const int n0 = blockIdx.x * BN;

    const int lane = tid & 31, wid = tid >> 5;
    const int wm0 = (wid >> 2) * 64;      // 0 / 64
    const int wn0 = (wid & 3) * 32;       // 0 / 32 / 64 / 96

    float acc[4][4][4];
#pragma unroll
    for (int i = 0; i < 4; i++)
#pragma unroll
        for (int j = 0; j < 4; j++)
#pragma unroll
            for (int k = 0; k < 4; k++) acc[i][j][k] = 0.f;

    // ldmatrix lane address components
    const int a_row = lane & 15;
    const int a_k   = (lane >> 4) << 3;                 // 0 / 8
    const int b_row = (lane & 7) + ((lane >> 1) & 8);   // +8 if bit4
    const int b_k   = ((lane >> 3) & 1) << 3;           // +8 if bit3

    const int nIter = K >> 6;

    // ---------------- stage loader (cp.async) ----------------
    auto load_stage = [&](int it, int s) {
        const long long k0 = (long long)it * BKC;
        const uint32_t st = sb + s * STAGE;
#pragma unroll
        for (int j = 0; j < 4; j++) {
            int idx = tid + j * 256;            // 0..1023
            int r = idx >> 3, c = idx & 7;      // 128 rows x 8 chunks(16B)
            uint32_t so = r * (PADK * 2) + c * 16;
            long long ga = (long long)(m0 + r) * K + k0 + c * 8;
            long long gb = (long long)(n0 + r) * K + k0 + c * 8;
            CP16(st + 0 * ARR + so, (const char*)(Ahi + ga));
            CP16(st + 1 * ARR + so, (const char*)(Alo + ga));
            CP16(st + 2 * ARR + so, (const char*)(Bhi + gb));
            CP16(st + 3 * ARR + so, (const char*)(Blo + gb));
        }
        asm volatile("cp.async.commit_group;" ::: "memory");
    };

    load_stage(0, 0);

    for (int it = 0; it < nIter; ++it) {
        asm volatile("cp.async.wait_group 0;" ::: "memory");
        __syncthreads();
        if (it + 1 < nIter) load_stage(it + 1, (it + 1) & 1);

        const uint32_t st = sb + (it & 1) * STAGE;
#pragma unroll
        for (int kk = 0; kk < BKC; kk += 16) {
            uint32_t ah[4][4], al[4][4], bh[2][4], bl[2][4];
#pragma unroll
            for (int mt = 0; mt < 4; mt++) {
                uint32_t ad = st + (wm0 + 16 * mt + a_row) * (PADK * 2)
                            + (kk + a_k) * 2;
                LDSM4(ah[mt], ad);
                LDSM4(al[mt], ad + ARR);
            }
#pragma unroll
            for (int gq = 0; gq < 2; gq++) {
                uint32_t bd = st + 2 * ARR
                            + (wn0 + gq * 16 + b_row) * (PADK * 2)
                            + (kk + b_k) * 2;
                LDSM4(bh[gq], bd);
                LDSM4(bl[gq], bd + ARR);
            }
            // term 1: Ah * Bh
#pragma unroll
            for (int mt = 0; mt < 4; mt++)
#pragma unroll
                for (int nt = 0; nt < 4; nt++)
                    MMA(acc[mt][nt], ah[mt], bh[nt >> 1][(nt & 1) * 2],
                        bh[nt >> 1][(nt & 1) * 2 + 1]);
            // term 2: Ah * Bl
#pragma unroll
            for (int mt = 0; mt < 4; mt++)
#pragma unroll
                for (int nt = 0; nt < 4; nt++)
                    MMA(acc[mt][nt], ah[mt], bl[nt >> 1][(nt & 1) * 2],
                        bl[nt >> 1][(nt & 1) * 2 + 1]);
            // term 3: Al * Bh
#pragma unroll
            for (int mt = 0; mt < 4; mt++)
#pragma unroll
                for (int nt = 0; nt < 4; nt++)
                    MMA(acc[mt][nt], al[mt], bh[nt >> 1][(nt & 1) * 2],
                        bh[nt >> 1][(nt & 1) * 2 + 1]);
        }
        __syncthreads();
    }

    // ---------------------------- epilogue ---------------------------------
    const int g2 = lane >> 2;
    const int t2 = (lane & 3) * 2;
#pragma unroll
    for (int mt = 0; mt < 4; mt++) {
#pragma unroll
        for (int hf = 0; hf < 2; hf++) {
            int row = m0 + wm0 + mt * 16 + g2 + hf * 8;
            bool msk = (mask != nullptr) && (mask[row] == 0);
#pragma unroll
            for (int nt = 0; nt < 4; nt++) {
                int col = n0 + wn0 + nt * 8 + t2;
                float v0 = acc[mt][nt][hf * 2 + 0];
                float v1 = acc[mt][nt][hf * 2 + 1];
                if (bias) { v0 += __ldg(bias + col); v1 += __ldg(bias + col + 1); }
                if (msk)  { v0 = NEGV; v1 = NEGV; }
                long long o = coff + (long long)row * ldc + col;
                if (Cf) {
                    float2 w; w.x = v0; w.y = v1;
                    *(float2*)(Cf + o) = w;
                } else {
                    __nv_bfloat16 h0 = __float2bfloat16(v0);
                    __nv_bfloat16 h1 = __float2bfloat16(v1);
                    __nv_bfloat16 l0 = __float2bfloat16(v0 - __bfloat162float(h0));
                    __nv_bfloat16 l1 = __float2bfloat16(v1 - __bfloat162float(h1));
                    __nv_bfloat162 hh; hh.x = h0; hh.y = h1;
                    __nv_bfloat162 ll; ll.x = l0; ll.y = l1;
                    *(__nv_bfloat162*)(Chi + o) = hh;
                    *(__nv_bfloat162*)(Clo + o) = ll;
                }
            }
        }
    }
}

// ===================== softmax (writes split-bf16 P) ========================
__global__ __launch_bounds__(256)
void softmax_split_kernel(const float* __restrict__ att,
                          __nv_bfloat16* __restrict__ Ph,
                          __nv_bfloat16* __restrict__ Pl)
{
    __shared__ float red[256];
    __shared__ float ev[NVV];
    const int row = blockIdx.x;
    const float* a = att + (long long)row * NVV;
    const int tid = threadIdx.x;

    float mx = -INFINITY;
    for (int c = tid; c < NVV; c += 256) mx = fmaxf(mx, a[c]);
    red[tid] = mx; __syncthreads();
    for (int s = 128; s > 0; s >>= 1) {
        if (tid < s) red[tid] = fmaxf(red[tid], red[tid + s]);
        __syncthreads();
    }
    mx = red[0]; __syncthreads();

    float sum = 0.f;
    for (int c = tid; c < NVV; c += 256) {
        float e = __expf(a[c] - mx);
        ev[c] = e;
        sum += e;
    }
    red[tid] = sum; __syncthreads();
    for (int s = 128; s > 0; s >>= 1) {
        if (tid < s) red[tid] += red[tid + s];
        __syncthreads();
    }
    float inv = 1.f / red[0];
    for (int c = tid; c < NVV; c += 256) {
        float v = ev[c] * inv;
        __nv_bfloat16 h = __float2bfloat16(v);
        long long o = (long long)row * NVV + c;
        Ph[o] = h;
        Pl[o] = __float2bfloat16(v - __bfloat162float(h));
    }
}

// ===================== elementwise tail =====================================
__global__ __launch_bounds__(256)
void s_kernel(const float* __restrict__ Vp, const float* __restrict__ Hv,
              const float* __restrict__ Zp, float* __restrict__ zout)
{
    long long i = (long long)blockIdx.x * 256 + threadIdx.x;
    float x = Vp[i] + Hv[i] + Zp[i];
    float s = 1.f / (1.f + __expf(-x));
    long long row = i >> 10;
    int col = (int)(i & 1023);
    zout[row * 2048 + col] = s;
}

__global__ __launch_bounds__(256)
void u_kernel(const float* __restrict__ zout, const float* __restrict__ Wu,
              float* __restrict__ u)
{
    __shared__ float red[256];
    const int row = blockIdx.x;
    const float* s = zout + (long long)row * 2048;
    const int tid = threadIdx.x;
    float acc = 0.f;
    for (int d = tid; d < DD; d += 256) acc = fmaf(s[d], Wu[d], acc);
    red[tid] = acc; __syncthreads();
    for (int st = 128; st > 0; st >>= 1) {
        if (tid < st) red[tid] += red[tid + st];
        __syncthreads();
    }
    if (tid == 0) u[row] = red[0];
}

__global__ __launch_bounds__(256)
void p_kernel(const float* __restrict__ u, const int* __restrict__ v_mask,
              float* __restrict__ p)
{
    __shared__ float red[256];
    __shared__ float vals[NVV];
    const int b = blockIdx.x;
    const int tid = threadIdx.x;

    float mx = -INFINITY;
    for (int j = tid; j < NVV; j += 256) {
        float val = (v_mask[b * NVV + j] == 0) ? NEGV : u[b * NVV + j];
        vals[j] = val;
        mx = fmaxf(mx, val);
    }
    red[tid] = mx; __syncthreads();
    for (int s = 128; s > 0; s >>= 1) {
        if (tid < s) red[tid] = fmaxf(red[tid], red[tid + s]);
        __syncthreads();
    }
    mx = red[0]; __syncthreads();

    float sum = 0.f;
    for (int j = tid; j < NVV; j += 256) {
        float e = __expf(vals[j] - mx);
        vals[j] = e;
        sum += e;
    }
    red[tid] = sum; __syncthreads();
    for (int s = 128; s > 0; s >>= 1) {
        if (tid < s) red[tid] += red[tid + s];
        __syncthreads();
    }
    float inv = 1.f / red[0];
    for (int j = tid; j < NVV; j += 256) p[b * NVV + j] = vals[j] * inv;
}

__global__ __launch_bounds__(256)
void g_kernel(const float* __restrict__ p, const float* __restrict__ v,
              float* __restrict__ g)
{
    __shared__ float ps[NVV];
    const int b = blockIdx.y;
    const int tid = threadIdx.x;
    for (int j = tid; j < NVV; j += 256) ps[j] = p[b * NVV + j];
    __syncthreads();
    const int d = blockIdx.x * 256 + tid;
    const float* vb = v + (long long)b * NVV * DD;
    float acc = 0.f;
#pragma unroll 4
    for (int j = 0; j < NVV; j++)
        acc = fmaf(ps[j], vb[(long long)j * DD + d], acc);
    g[b * DD + d] = acc;
}

__global__ __launch_bounds__(256)
void bcast_kernel(const float* __restrict__ g, float* __restrict__ hnew,
                  float* __restrict__ zout)
{
    long long i = (long long)blockIdx.x * 256 + threadIdx.x;
    int d = (int)(i & 1023);
    long long bi = i >> 10;
    int b = (int)(bi >> 10);
    float val = g[b * DD + d];
    hnew[i] = val;
    zout[bi * 2048 + DD + d] = val;
}

// ================================ launch ====================================
extern "C" void kernel_launch(void* const* d_in, const int* in_sizes, int n_in,
                              void* d_out, int out_size)
{
    const float* v      = (const float*)d_in[0];
    const float* h      = (const float*)d_in[1];
    const float* z      = (const float*)d_in[2];
    const int*   v_mask = (const int*)  d_in[3];
    const int*   h_mask = (const int*)  d_in[4];
    const float* Wv_w   = (const float*)d_in[5];
    const float* Wv_b   = (const float*)d_in[6];
    const float* Wh_w   = (const float*)d_in[7];
    const float* qv_w   = (const float*)d_in[8];
    const float* qv_b   = (const float*)d_in[9];
    const float* kh_w   = (const float*)d_in[10];
    const float* Wz_w   = (const float*)d_in[11];
    const float* Wu_w   = (const float*)d_in[12];

    float* out  = (float*)d_out;
    float* hnew = out;
    float* zout = out + (long long)MROWS * DD;

    cudaFuncSetAttribute(gemm_split, cudaFuncAttributeMaxDynamicSharedMemorySize,
                         SMEM_GEMM);

#define SYM(p, s) do { void* _t; cudaGetSymbolAddress(&_t, s); p = (decltype(p))_t; } while (0)
    __nv_bfloat16 *vhi, *vlo, *hhi, *hlo, *zhi, *zlo;
    __nv_bfloat16 *Wvh, *Wvl, *qvh, *qvl, *Whh, *Whl, *khh, *khl, *Wzh, *Wzl;
    __nv_bfloat16 *Qh, *Ql, *Kh, *Kl, *Ph, *Pl, *HTh, *HTl;
    float *Vp, *Hh, *Zp, *Att, *Hv, *U, *P, *G;
    SYM(vhi, g_vhi); SYM(vlo, g_vlo); SYM(hhi, g_hhi); SYM(hlo, g_hlo);
    SYM(zhi, g_zhi); SYM(zlo, g_zlo);
    SYM(Wvh, g_Wvh); SYM(Wvl, g_Wvl); SYM(qvh, g_qvh); SYM(qvl, g_qvl);
    SYM(Whh, g_Whh); SYM(Whl, g_Whl); SYM(khh, g_khh); SYM(khl, g_khl);
    SYM(Wzh, g_Wzh); SYM(Wzl, g_Wzl);
    SYM(Qh, g_Qh); SYM(Ql, g_Ql); SYM(Kh, g_Kh); SYM(Kl, g_Kl);
    SYM(Ph, g_Ph); SYM(Pl, g_Pl); SYM(HTh, g_HTh); SYM(HTl, g_HTl);
    SYM(Vp, g_Vp); SYM(Hh, g_Hh); SYM(Zp, g_Zp); SYM(Att, g_att); SYM(Hv, g_Hv);
    SYM(U, g_u); SYM(P, g_p); SYM(G, g_g);
#undef SYM

    // ---- fp32 -> split bf16 conversions ----
    auto conv = [&](const float* x, __nv_bfloat16* hi, __nv_bfloat16* lo, long long n) {
        long long n4 = n >> 2;
        conv_split<<<(unsigned)((n4 + 255) / 256), 256>>>(x, hi, lo, n4);
    };
    conv(v, vhi, vlo, (long long)MROWS * DD);
    conv(h, hhi, hlo, (long long)MROWS * DD);
    conv(z, zhi, zlo, (long long)MROWS * 2 * DD);
    conv(Wv_w, Wvh, Wvl, (long long)DD * DD);
    conv(qv_w, qvh, qvl, (long long)DD * DD);
    conv(Wh_w, Whh, Whl, (long long)DD * DD);
    conv(kh_w, khh, khl, (long long)DD * DD);
    conv(Wz_w, Wzh, Wzl, (long long)DD * 2 * DD);

    const long long PB = (long long)NVV * NVV;
    dim3 gBig(DD / BN, MROWS / BM, 1);     // (8,128,1)
    dim3 gBat(DD / BN, NVV / BM, BB);      // (8,8,16)

    // ---- projections ----
    gemm_split<<<gBig, 256, SMEM_GEMM>>>(vhi, vlo, Wvh, Wvl, Wv_b, nullptr,
                                         Vp, nullptr, nullptr, DD, DD, 0, 0, 0);
    gemm_split<<<gBig, 256, SMEM_GEMM>>>(vhi, vlo, qvh, qvl, qv_b, nullptr,
                                         nullptr, Qh, Ql, DD, DD, 0, 0, 0);
    gemm_split<<<gBig, 256, SMEM_GEMM>>>(hhi, hlo, Whh, Whl, nullptr, nullptr,
                                         Hh, nullptr, nullptr, DD, DD, 0, 0, 0);
    gemm_split<<<gBig, 256, SMEM_GEMM>>>(hhi, hlo, khh, khl, nullptr, h_mask,
                                         nullptr, Kh, Kl, DD, DD, 0, 0, 0);
    gemm_split<<<gBig, 256, SMEM_GEMM>>>(zhi, zlo, Wzh, Wzl, nullptr, nullptr,
                                         Zp, nullptr, nullptr, 2 * DD, DD, 0, 0, 0);

    // ---- attention ----
    gemm_split<<<gBat, 256, SMEM_GEMM>>>(Qh, Ql, Kh, Kl, nullptr, nullptr,
                                         Att, nullptr, nullptr, DD, NVV, PB, PB, PB);
    softmax_split_kernel<<<MROWS, 256>>>(Att, Ph, Pl);
    transconv_kernel<<<dim3(32, 32, BB), dim3(32, 8)>>>(Hh, HTh, HTl);
    gemm_split<<<gBat, 256, SMEM_GEMM>>>(Ph, Pl, HTh, HTl, nullptr, nullptr,
                                         Hv, nullptr, nullptr, NVV, DD, PB, PB, PB);

    // ---- tail ----
    s_kernel<<<(MROWS * DD) / 256, 256>>>(Vp, Hv, Zp, zout);
    u_kernel<<<MROWS, 256>>>(zout, Wu_w, U);
    p_kernel<<<BB, 256>>>(U, v_mask, P);
    g_kernel<<<dim3(DD / 256, BB), 256>>>(P, v, G);
    bcast_kernel<<<(MROWS * DD) / 256, 256>>>(G, hnew, zout);
}